// round 16
// baseline (speedup 1.0000x reference)
#include <cuda_runtime.h>
#include <cuda_fp16.h>
#include <cstdint>

#define NN    10000
#define HEADS 4
#define F     256      // heads * 64, also input feature count
#define EMAX  340000   // 320000 edges + 10000 self loops, padded

// ---------------- persistent scratch (no allocation allowed) ----------------
__device__ uint32_t g_h16[NN * (F / 2)];   // h as half2 pairs: [node][128]
__device__ uint32_t g_ah[NN * (F / 2)];    // x as half2 (prep-converted)
__device__ uint32_t g_featH[NN * (F / 2)]; // layer activations as half2
__device__ uint32_t g_bh[3 * 128 * 256];   // W1|W2|W3 as half2 (32768 u32 each)
__device__ float    g_as[NN * HEADS];      // per-node src attention logits
__device__ float    g_ad[NN * HEADS];      // per-node dst attention logits
__device__ float    g_w[EMAX * HEADS];     // edge logits -> normalized weights
__device__ int      g_deg[NN];             // zero at load; re-zeroed by scatter
__device__ int      g_ptr[NN + 1];
__device__ int      g_epos[EMAX];          // per-edge position within its dst bucket
__device__ int      g_srcb[EMAX];          // CSR-by-dst: src node per slot
__device__ int      g_is64;                // edge_index dtype flag
__device__ int      g_ctr;                 // count_scan last-block counter

// ---------------- edge dtype detection (1 warp) ----------------
__global__ void detect_kernel(const void* eiv) {
    if (threadIdx.x == 0) {
        const long long* p = (const long long*)eiv;
        int ok = 1;
        for (int i = 0; i < 64; i++) {
            long long v = p[i];
            if (v < 0 || v >= NN) { ok = 0; break; }
        }
        g_is64 = ok;
    }
}

// ------------- prep: fp32 -> fp16 for x and weights -------------------------
__global__ void prep_kernel(const float* x, const float* W1, const float* W2,
                            const float* W3) {
    int t = blockIdx.x * blockDim.x + threadIdx.x;
    const int NX = NN * 128;       // x half2 count
    const int NW = 32768;          // per-weight half2 count
    if (t < NX) {
        float2 v = ((const float2*)x)[t];
        __half2 h = __floats2half2_rn(v.x, v.y);
        g_ah[t] = *(uint32_t*)&h;
    } else if (t < NX + NW) {
        int i = t - NX;
        float2 v = ((const float2*)W1)[i];
        __half2 h = __floats2half2_rn(v.x, v.y);
        g_bh[i] = *(uint32_t*)&h;
    } else if (t < NX + 2 * NW) {
        int i = t - NX - NW;
        float2 v = ((const float2*)W2)[i];
        __half2 h = __floats2half2_rn(v.x, v.y);
        g_bh[NW + i] = *(uint32_t*)&h;
    } else if (t < NX + 3 * NW) {
        int i = t - NX - 2 * NW;
        float2 v = ((const float2*)W3)[i];
        __half2 h = __floats2half2_rn(v.x, v.y);
        g_bh[2 * NW + i] = *(uint32_t*)&h;
    }
}

// ------- CSR count (4 edges/thread) + fused scan (last block) ---------------
__global__ void count_scan_kernel(const void* eiv, int E) {
    __shared__ int sdeg[NN];
    __shared__ int wsum[8];
    __shared__ int isLast;

    int t = blockIdx.x * blockDim.x + threadIdx.x;
    int nv = E >> 2, rem = E & 3;
    if (t < nv) {
        int d0, d1, d2, d3;
        if (!g_is64) {
            const int4* p = (const int4*)((const int*)eiv + E);
            int4 d = p[t];
            d0 = d.x; d1 = d.y; d2 = d.z; d3 = d.w;
        } else {
            const longlong2* p = (const longlong2*)((const long long*)eiv + E);
            longlong2 a = p[2 * t], b = p[2 * t + 1];
            d0 = (int)a.x; d1 = (int)a.y; d2 = (int)b.x; d3 = (int)b.y;
        }
        int4 pos;
        pos.x = atomicAdd(&g_deg[d0], 1);
        pos.y = atomicAdd(&g_deg[d1], 1);
        pos.z = atomicAdd(&g_deg[d2], 1);
        pos.w = atomicAdd(&g_deg[d3], 1);
        *(int4*)&g_epos[t * 4] = pos;
    } else if (t < nv + rem) {
        int idx = nv * 4 + (t - nv);
        int d = g_is64 ? (int)((const long long*)eiv)[E + idx]
                       : ((const int*)eiv)[E + idx];
        g_epos[idx] = atomicAdd(&g_deg[d], 1);
    } else if (t < nv + rem + NN) {
        int i = t - nv - rem;
        g_epos[E + i] = atomicAdd(&g_deg[i], 1);  // self loop
    }

    // last-arriving block performs the exclusive scan
    __threadfence();
    if (threadIdx.x == 0)
        isLast = (atomicAdd(&g_ctr, 1) == (int)gridDim.x - 1);
    __syncthreads();
    if (!isLast) return;

    int tid = threadIdx.x;
    for (int i = tid; i < NN; i += 256) sdeg[i] = g_deg[i];
    __syncthreads();

    const int CH = (NN + 255) / 256;  // 40
    int base = tid * CH;
    int tot = 0;
    for (int i = 0; i < CH; i++) {
        int idx = base + i;
        if (idx < NN) tot += sdeg[idx];
    }
    int lane = tid & 31, wid = tid >> 5;
    int v = tot;
    for (int off = 1; off < 32; off <<= 1) {
        int u = __shfl_up_sync(0xffffffffu, v, off);
        if (lane >= off) v += u;
    }
    if (lane == 31) wsum[wid] = v;
    __syncthreads();
    if (wid == 0) {
        int w = (lane < 8) ? wsum[lane] : 0;
        for (int off = 1; off < 8; off <<= 1) {
            int u = __shfl_up_sync(0xffffffffu, w, off);
            if (lane >= off) w += u;
        }
        if (lane < 8) wsum[lane] = w;
    }
    __syncthreads();
    int run = v - tot + (wid ? wsum[wid - 1] : 0);
    for (int i = 0; i < CH; i++) {
        int idx = base + i;
        if (idx < NN) {
            int d = sdeg[idx];
            sdeg[idx] = run;
            run += d;
        }
    }
    if (tid == 255) g_ptr[NN] = run;
    __syncthreads();
    for (int i = tid; i < NN; i += 256) g_ptr[i] = sdeg[i];
    if (tid == 0) g_ctr = 0;   // reset for next graph replay
}

// scatter: NO atomics — slot = g_ptr[dst] + precomputed position.
__global__ void scatter_kernel(const void* eiv, int E) {
    int t = blockIdx.x * blockDim.x + threadIdx.x;
    int nv = E >> 2, rem = E & 3;
    if (t < nv) {
        int s0, s1, s2, s3, d0, d1, d2, d3;
        if (!g_is64) {
            const int4* ps = (const int4*)eiv;
            const int4* pd = (const int4*)((const int*)eiv + E);
            int4 s = ps[t], d = pd[t];
            s0 = s.x; s1 = s.y; s2 = s.z; s3 = s.w;
            d0 = d.x; d1 = d.y; d2 = d.z; d3 = d.w;
        } else {
            const longlong2* ps = (const longlong2*)eiv;
            const longlong2* pd = (const longlong2*)((const long long*)eiv + E);
            longlong2 sa = ps[2 * t], sb = ps[2 * t + 1];
            longlong2 da = pd[2 * t], db = pd[2 * t + 1];
            s0 = (int)sa.x; s1 = (int)sa.y; s2 = (int)sb.x; s3 = (int)sb.y;
            d0 = (int)da.x; d1 = (int)da.y; d2 = (int)db.x; d3 = (int)db.y;
        }
        int4 pos = *(const int4*)&g_epos[t * 4];
        g_srcb[g_ptr[d0] + pos.x] = s0;
        g_srcb[g_ptr[d1] + pos.y] = s1;
        g_srcb[g_ptr[d2] + pos.z] = s2;
        g_srcb[g_ptr[d3] + pos.w] = s3;
    } else if (t < nv + rem) {
        int idx = nv * 4 + (t - nv);
        int s, d;
        if (g_is64) {
            s = (int)((const long long*)eiv)[idx];
            d = (int)((const long long*)eiv)[E + idx];
        } else {
            s = ((const int*)eiv)[idx];
            d = ((const int*)eiv)[E + idx];
        }
        g_srcb[g_ptr[d] + g_epos[idx]] = s;
    } else if (t < nv + rem + NN) {
        int i = t - nv - rem;
        g_srcb[g_ptr[i] + g_epos[E + i]] = i;
        g_deg[i] = 0;   // ready for next replay
    }
}

// ------ fp16 tensor-core GEMM (m16n8k16), fp16-native staging ---------------
template <bool USE_FEAT>
__global__ void __launch_bounds__(256) gemm_f16_kernel(int bOff,
                                                       const float* att_s,
                                                       const float* att_d) {
    __shared__ __half As[128][40];   // pad 40 halves
    __shared__ __half Bs[32][72];    // pad 72 halves
    __shared__ float sAs[128], sAd[128];
    int tid = threadIdx.x;
    int wid = tid >> 5, lane = tid & 31;
    int wm = wid >> 1, wn = wid & 1;
    int m0 = blockIdx.x * 128, n0 = blockIdx.y * 64;
    int hd = blockIdx.y;

    if (tid < 128) { sAs[tid] = 0.f; sAd[tid] = 0.f; }

    float c[2][4][4];
#pragma unroll
    for (int f = 0; f < 2; f++)
#pragma unroll
        for (int g = 0; g < 4; g++)
#pragma unroll
            for (int i = 0; i < 4; i++) c[f][g][i] = 0.f;

    int lr = lane >> 2;   // 0..7
    int lc = lane & 3;    // 0..3

    for (int kt = 0; kt < F; kt += 32) {
#pragma unroll
        for (int i = 0; i < 2; i++) {
            int id = tid + i * 256;
            int row = id >> 2, seg = id & 3;
            int m = m0 + row;
            uint4 v = make_uint4(0, 0, 0, 0);
            if (m < NN) {
                const uint32_t* src = (USE_FEAT ? g_featH : g_ah)
                                    + (long)m * 128 + (kt >> 1) + seg * 4;
                v = *(const uint4*)src;
            }
            *(uint4*)&As[row][seg * 8] = v;
        }
        {
            int row = tid >> 3, seg = tid & 7;
            const uint32_t* src = g_bh + bOff + (long)(kt + row) * 128
                                + (n0 >> 1) + seg * 4;
            *(uint4*)&Bs[row][seg * 8] = *(const uint4*)src;
        }
        __syncthreads();

#pragma unroll
        for (int s = 0; s < 2; s++) {       // two k16 steps per 32-chunk
            int kb = s * 16;
            uint32_t a[2][4];
#pragma unroll
            for (int f = 0; f < 2; f++) {
                int rb = wm * 32 + f * 16;
                a[f][0] = *(const uint32_t*)&As[rb + lr][kb + 2 * lc];
                a[f][1] = *(const uint32_t*)&As[rb + lr + 8][kb + 2 * lc];
                a[f][2] = *(const uint32_t*)&As[rb + lr][kb + 2 * lc + 8];
                a[f][3] = *(const uint32_t*)&As[rb + lr + 8][kb + 2 * lc + 8];
            }
            uint32_t b[4][2];
#pragma unroll
            for (int g = 0; g < 4; g++) {
                int cb = wn * 32 + g * 8 + lr;
                uint16_t lo0 = __half_as_ushort(Bs[kb + 2 * lc][cb]);
                uint16_t hi0 = __half_as_ushort(Bs[kb + 2 * lc + 1][cb]);
                uint16_t lo1 = __half_as_ushort(Bs[kb + 2 * lc + 8][cb]);
                uint16_t hi1 = __half_as_ushort(Bs[kb + 2 * lc + 9][cb]);
                b[g][0] = (uint32_t)lo0 | ((uint32_t)hi0 << 16);
                b[g][1] = (uint32_t)lo1 | ((uint32_t)hi1 << 16);
            }
#pragma unroll
            for (int f = 0; f < 2; f++)
#pragma unroll
                for (int g = 0; g < 4; g++) {
                    asm volatile(
                        "mma.sync.aligned.m16n8k16.row.col.f32.f16.f16.f32 "
                        "{%0,%1,%2,%3}, {%4,%5,%6,%7}, {%8,%9}, {%0,%1,%2,%3};"
                        : "+f"(c[f][g][0]), "+f"(c[f][g][1]),
                          "+f"(c[f][g][2]), "+f"(c[f][g][3])
                        : "r"(a[f][0]), "r"(a[f][1]), "r"(a[f][2]), "r"(a[f][3]),
                          "r"(b[g][0]), "r"(b[g][1]));
                }
        }
        __syncthreads();
    }

    // epilogue: write h as half2, fused per-row attention dots (fp32)
#pragma unroll
    for (int f = 0; f < 2; f++) {
        int row0 = m0 + wm * 32 + f * 16 + lr;
        float ps0 = 0.f, ps1 = 0.f, pd0 = 0.f, pd1 = 0.f;
#pragma unroll
        for (int g = 0; g < 4; g++) {
            int colh = wn * 32 + g * 8 + lc * 2;        // column within head
            float as0 = att_s[hd * 64 + colh], as1 = att_s[hd * 64 + colh + 1];
            float ad0 = att_d[hd * 64 + colh], ad1 = att_d[hd * 64 + colh + 1];
            ps0 += c[f][g][0] * as0 + c[f][g][1] * as1;
            pd0 += c[f][g][0] * ad0 + c[f][g][1] * ad1;
            ps1 += c[f][g][2] * as0 + c[f][g][3] * as1;
            pd1 += c[f][g][2] * ad0 + c[f][g][3] * ad1;
            uint32_t hidx = (uint32_t)(wn * 16 + g * 4 + lc) + hd * 32;
            if (row0 < NN) {
                __half2 hv = __floats2half2_rn(c[f][g][0], c[f][g][1]);
                g_h16[(long)row0 * 128 + hidx] = *(uint32_t*)&hv;
            }
            if (row0 + 8 < NN) {
                __half2 hv = __floats2half2_rn(c[f][g][2], c[f][g][3]);
                g_h16[(long)(row0 + 8) * 128 + hidx] = *(uint32_t*)&hv;
            }
        }
#pragma unroll
        for (int off = 1; off <= 2; off <<= 1) {
            ps0 += __shfl_xor_sync(0xffffffffu, ps0, off);
            ps1 += __shfl_xor_sync(0xffffffffu, ps1, off);
            pd0 += __shfl_xor_sync(0xffffffffu, pd0, off);
            pd1 += __shfl_xor_sync(0xffffffffu, pd1, off);
        }
        if (lc == 0) {
            int r = wm * 32 + f * 16 + lr;
            atomicAdd(&sAs[r], ps0);
            atomicAdd(&sAd[r], pd0);
            atomicAdd(&sAs[r + 8], ps1);
            atomicAdd(&sAd[r + 8], pd1);
        }
    }
    __syncthreads();
    if (tid < 128) {
        int m = m0 + tid;
        if (m < NN) {
            g_as[m * HEADS + hd] = sAs[tid];
            g_ad[m * HEADS + hd] = sAd[tid];
        }
    }
}

// ------- pass 1 + weights: one warp per node, all 4 heads -------------------
__global__ void agg1w_kernel() {
    int n = (blockIdx.x * blockDim.x + threadIdx.x) >> 5;
    int lane = threadIdx.x & 31;
    if (n >= NN) return;
    int hd = lane & 3, sub = lane >> 2;
    int beg = g_ptr[n], end = g_ptr[n + 1];
    float ad = g_ad[n * HEADS + hd];

    float m = -1e30f, s = 0.f;
    for (int j = beg + sub; j < end; j += 8) {
        int src = g_srcb[j];
        float e = g_as[src * HEADS + hd] + ad;
        e = (e > 0.f) ? e : 0.2f * e;
        g_w[j * HEADS + hd] = e;          // stash raw logit (coalesced)
        float mn = fmaxf(m, e);
        s = s * __expf(m - mn) + __expf(e - mn);
        m = mn;
    }
#pragma unroll
    for (int off = 4; off <= 16; off <<= 1) {
        float m2 = __shfl_xor_sync(0xffffffffu, m, off);
        float s2 = __shfl_xor_sync(0xffffffffu, s, off);
        float mn = fmaxf(m, m2);
        s = s * __expf(m - mn) + s2 * __expf(m2 - mn);
        m = mn;
    }
    float inv = 1.f / (s + 1e-16f);

    for (int j = beg + sub; j < end; j += 8) {
        float e = g_w[j * HEADS + hd];    // coalesced reload
        g_w[j * HEADS + hd] = __expf(e - m) * inv;
    }
}

// ------- pass 2: weighted gather — warp per (node, head), 8-wide MLP --------
template <bool TO_FEAT>
__global__ void agg2_kernel(const float* bias, float* outext) {
    int gw = (blockIdx.x * blockDim.x + threadIdx.x) >> 5;
    int lane = threadIdx.x & 31;
    if (gw >= NN * HEADS) return;
    int n = gw >> 2, hd = gw & 3;
    int beg = g_ptr[n], end = g_ptr[n + 1];
    const int hoff32 = hd * 32;

    float acc0 = 0.f, acc1 = 0.f;
    int j = beg;
    for (; j + 8 <= end; j += 8) {
        int si[8]; float wi[8]; uint32_t ui[8];
#pragma unroll
        for (int k = 0; k < 8; k++) si[k] = g_srcb[j + k];
#pragma unroll
        for (int k = 0; k < 8; k++) wi[k] = g_w[(j + k) * HEADS + hd];
#pragma unroll
        for (int k = 0; k < 8; k++)
            ui[k] = g_h16[(long)si[k] * 128 + hoff32 + lane];
#pragma unroll
        for (int k = 0; k < 8; k++) {
            float2 f = __half22float2(*(__half2*)&ui[k]);
            acc0 += wi[k] * f.x;
            acc1 += wi[k] * f.y;
        }
    }
    for (; j < end; ++j) {
        int s0 = g_srcb[j];
        float w0 = g_w[j * HEADS + hd];
        uint32_t u0 = g_h16[(long)s0 * 128 + hoff32 + lane];
        float2 f0 = __half22float2(*(__half2*)&u0);
        acc0 += w0 * f0.x;
        acc1 += w0 * f0.y;
    }

    int col = hd * 64 + lane * 2;
    float v0 = acc0 + bias[col];
    float v1 = acc1 + bias[col + 1];
    v0 = (v0 > 0.f) ? v0 : (__expf(v0) - 1.f);  // ELU
    v1 = (v1 > 0.f) ? v1 : (__expf(v1) - 1.f);
    if (TO_FEAT) {
        __half2 hv = __floats2half2_rn(v0, v1);
        g_featH[(long)n * 128 + hoff32 + lane] = *(uint32_t*)&hv;
    } else {
        *(float2*)&outext[(long)n * F + col] = make_float2(v0, v1);
    }
}

// ---------------- orchestration ----------------
extern "C" void kernel_launch(void* const* d_in, const int* in_sizes, int n_in,
                              void* d_out, int out_size) {
    const float* x   = (const float*)d_in[0];
    const void*  ei  = d_in[1];
    const float* W1  = (const float*)d_in[2];
    const float* a1s = (const float*)d_in[3];
    const float* a1d = (const float*)d_in[4];
    const float* b1  = (const float*)d_in[5];
    const float* W2  = (const float*)d_in[6];
    const float* a2s = (const float*)d_in[7];
    const float* a2d = (const float*)d_in[8];
    const float* b2  = (const float*)d_in[9];
    const float* W3  = (const float*)d_in[10];
    const float* a3s = (const float*)d_in[11];
    const float* a3d = (const float*)d_in[12];
    const float* b3  = (const float*)d_in[13];
    float* out = (float*)d_out;
    int E = in_sizes[1] / 2;
    int nthreads = (E >> 2) + (E & 3) + NN;
    int prepThreads = NN * 128 + 3 * 32768;

    dim3 ggrid((NN + 127) / 128, F / 64);
    int p1Blocks = (NN * 32 + 255) / 256;
    int p2Blocks = (NN * HEADS * 32 + 255) / 256;

    // Fork: CSR chain on per-thread stream, prep + GEMM1 on legacy stream.
    cudaEvent_t evFork, evJoin;
    cudaEventCreateWithFlags(&evFork, cudaEventDisableTiming);
    cudaEventCreateWithFlags(&evJoin, cudaEventDisableTiming);

    cudaEventRecord(evFork, 0);
    cudaStreamWaitEvent(cudaStreamPerThread, evFork, 0);

    detect_kernel<<<1, 32, 0, cudaStreamPerThread>>>(ei);
    count_scan_kernel<<<(nthreads + 255) / 256, 256, 0, cudaStreamPerThread>>>(ei, E);
    scatter_kernel<<<(nthreads + 255) / 256, 256, 0, cudaStreamPerThread>>>(ei, E);
    cudaEventRecord(evJoin, cudaStreamPerThread);

    prep_kernel<<<(prepThreads + 255) / 256, 256>>>(x, W1, W2, W3);
    gemm_f16_kernel<false><<<ggrid, 256>>>(0, a1s, a1d);

    cudaStreamWaitEvent(0, evJoin, 0);   // agg needs CSR + GEMM1

    // layer 1
    agg1w_kernel<<<p1Blocks, 256>>>();
    agg2_kernel<true><<<p2Blocks, 256>>>(b1, nullptr);

    // layer 2
    gemm_f16_kernel<true><<<ggrid, 256>>>(32768, a2s, a2d);
    agg1w_kernel<<<p1Blocks, 256>>>();
    agg2_kernel<true><<<p2Blocks, 256>>>(b2, nullptr);

    // layer 3
    gemm_f16_kernel<true><<<ggrid, 256>>>(65536, a3s, a3d);
    agg1w_kernel<<<p1Blocks, 256>>>();
    agg2_kernel<false><<<p2Blocks, 256>>>(b3, out);
}

// round 17
// speedup vs baseline: 1.0203x; 1.0203x over previous
#include <cuda_runtime.h>
#include <cuda_fp16.h>
#include <cstdint>

#define NN    10000
#define HEADS 4
#define F     256      // heads * 64, also input feature count
#define EMAX  340000   // 320000 edges + 10000 self loops, padded

// ---------------- persistent scratch (no allocation allowed) ----------------
__device__ uint32_t g_h16[NN * (F / 2)];   // h as half2 pairs: [node][128]
__device__ uint32_t g_featH[NN * (F / 2)]; // layer activations as half2
__device__ uint32_t g_bh[3 * 128 * 256];   // W1|W2|W3 as half2 (32768 u32 each)
__device__ float    g_as[NN * HEADS];      // per-node src attention logits
__device__ float    g_ad[NN * HEADS];      // per-node dst attention logits
__device__ float    g_w[EMAX * HEADS];     // edge logits -> normalized weights
__device__ int      g_deg[NN];             // zero at load; re-zeroed by scatter
__device__ int      g_ptr[NN + 1];
__device__ int      g_epos[EMAX];          // per-edge position within its dst bucket
__device__ int      g_srcb[EMAX];          // CSR-by-dst: src node per slot
__device__ int      g_is64;                // edge_index dtype flag

// ---------------- edge dtype detection (1 warp) ----------------
__global__ void detect_kernel(const void* eiv) {
    if (threadIdx.x == 0) {
        const long long* p = (const long long*)eiv;
        int ok = 1;
        for (int i = 0; i < 64; i++) {
            long long v = p[i];
            if (v < 0 || v >= NN) { ok = 0; break; }
        }
        g_is64 = ok;
    }
}

// ------------- prep: fp32 -> fp16 for the three weight matrices -------------
__global__ void prep_kernel(const float* W1, const float* W2, const float* W3) {
    int t = blockIdx.x * blockDim.x + threadIdx.x;
    const int NW = 32768;          // per-weight half2 count
    if (t < NW) {
        float2 v = ((const float2*)W1)[t];
        __half2 h = __floats2half2_rn(v.x, v.y);
        g_bh[t] = *(uint32_t*)&h;
    } else if (t < 2 * NW) {
        int i = t - NW;
        float2 v = ((const float2*)W2)[i];
        __half2 h = __floats2half2_rn(v.x, v.y);
        g_bh[NW + i] = *(uint32_t*)&h;
    } else if (t < 3 * NW) {
        int i = t - 2 * NW;
        float2 v = ((const float2*)W3)[i];
        __half2 h = __floats2half2_rn(v.x, v.y);
        g_bh[2 * NW + i] = *(uint32_t*)&h;
    }
}

// ---------------- CSR build (4 edges per thread, vectorized) ----------------
__global__ void count_kernel(const void* eiv, int E) {
    int t = blockIdx.x * blockDim.x + threadIdx.x;
    int nv = E >> 2, rem = E & 3;
    if (t < nv) {
        int d0, d1, d2, d3;
        if (!g_is64) {
            const int4* p = (const int4*)((const int*)eiv + E);
            int4 d = p[t];
            d0 = d.x; d1 = d.y; d2 = d.z; d3 = d.w;
        } else {
            const longlong2* p = (const longlong2*)((const long long*)eiv + E);
            longlong2 a = p[2 * t], b = p[2 * t + 1];
            d0 = (int)a.x; d1 = (int)a.y; d2 = (int)b.x; d3 = (int)b.y;
        }
        int4 pos;
        pos.x = atomicAdd(&g_deg[d0], 1);
        pos.y = atomicAdd(&g_deg[d1], 1);
        pos.z = atomicAdd(&g_deg[d2], 1);
        pos.w = atomicAdd(&g_deg[d3], 1);
        *(int4*)&g_epos[t * 4] = pos;
    } else if (t < nv + rem) {
        int idx = nv * 4 + (t - nv);
        int d = g_is64 ? (int)((const long long*)eiv)[E + idx]
                       : ((const int*)eiv)[E + idx];
        g_epos[idx] = atomicAdd(&g_deg[d], 1);
    } else if (t < nv + rem + NN) {
        int i = t - nv - rem;
        g_epos[E + i] = atomicAdd(&g_deg[i], 1);  // self loop
    }
}

__global__ void __launch_bounds__(512) scan_kernel() {
    __shared__ int sdeg[NN];
    __shared__ int wsum[16];
    const int CH = (NN + 511) / 512;  // 20
    int t = threadIdx.x;
    for (int i = t; i < NN; i += 512) sdeg[i] = g_deg[i];
    __syncthreads();

    int base = t * CH;
    int tot = 0;
    for (int i = 0; i < CH; i++) {
        int idx = base + i;
        if (idx < NN) tot += sdeg[idx];
    }
    int lane = t & 31, wid = t >> 5;
    int v = tot;
    for (int off = 1; off < 32; off <<= 1) {
        int u = __shfl_up_sync(0xffffffffu, v, off);
        if (lane >= off) v += u;
    }
    if (lane == 31) wsum[wid] = v;
    __syncthreads();
    if (wid == 0) {
        int w = (lane < 16) ? wsum[lane] : 0;
        for (int off = 1; off < 16; off <<= 1) {
            int u = __shfl_up_sync(0xffffffffu, w, off);
            if (lane >= off) w += u;
        }
        if (lane < 16) wsum[lane] = w;
    }
    __syncthreads();
    int run = v - tot + (wid ? wsum[wid - 1] : 0);
    for (int i = 0; i < CH; i++) {
        int idx = base + i;
        if (idx < NN) {
            int d = sdeg[idx];
            sdeg[idx] = run;
            run += d;
        }
    }
    if (t == 511) g_ptr[NN] = run;
    __syncthreads();
    for (int i = t; i < NN; i += 512) g_ptr[i] = sdeg[i];
}

// scatter: NO atomics — slot = g_ptr[dst] + precomputed position.
__global__ void scatter_kernel(const void* eiv, int E) {
    int t = blockIdx.x * blockDim.x + threadIdx.x;
    int nv = E >> 2, rem = E & 3;
    if (t < nv) {
        int s0, s1, s2, s3, d0, d1, d2, d3;
        if (!g_is64) {
            const int4* ps = (const int4*)eiv;
            const int4* pd = (const int4*)((const int*)eiv + E);
            int4 s = ps[t], d = pd[t];
            s0 = s.x; s1 = s.y; s2 = s.z; s3 = s.w;
            d0 = d.x; d1 = d.y; d2 = d.z; d3 = d.w;
        } else {
            const longlong2* ps = (const longlong2*)eiv;
            const longlong2* pd = (const longlong2*)((const long long*)eiv + E);
            longlong2 sa = ps[2 * t], sb = ps[2 * t + 1];
            longlong2 da = pd[2 * t], db = pd[2 * t + 1];
            s0 = (int)sa.x; s1 = (int)sa.y; s2 = (int)sb.x; s3 = (int)sb.y;
            d0 = (int)da.x; d1 = (int)da.y; d2 = (int)db.x; d3 = (int)db.y;
        }
        int4 pos = *(const int4*)&g_epos[t * 4];
        g_srcb[g_ptr[d0] + pos.x] = s0;
        g_srcb[g_ptr[d1] + pos.y] = s1;
        g_srcb[g_ptr[d2] + pos.z] = s2;
        g_srcb[g_ptr[d3] + pos.w] = s3;
    } else if (t < nv + rem) {
        int idx = nv * 4 + (t - nv);
        int s, d;
        if (g_is64) {
            s = (int)((const long long*)eiv)[idx];
            d = (int)((const long long*)eiv)[E + idx];
        } else {
            s = ((const int*)eiv)[idx];
            d = ((const int*)eiv)[E + idx];
        }
        g_srcb[g_ptr[d] + g_epos[idx]] = s;
    } else if (t < nv + rem + NN) {
        int i = t - nv - rem;
        g_srcb[g_ptr[i] + g_epos[E + i]] = i;
        g_deg[i] = 0;   // ready for next replay
    }
}

// ------ fp16 tensor-core GEMM (m16n8k16) ------------------------------------
// Layer 1 (USE_FEAT=false): A staged from fp32 Aext with cvt at STS (R13 path).
// Layers 2-3 (USE_FEAT=true): A staged as raw uint4 fp16 from g_featH (R14 path).
template <bool USE_FEAT>
__global__ void __launch_bounds__(256) gemm_f16_kernel(const float* Aext,
                                                       int bOff,
                                                       const float* att_s,
                                                       const float* att_d) {
    __shared__ __half As[128][40];   // pad 40 halves
    __shared__ __half Bs[32][72];    // pad 72 halves
    __shared__ float sAs[128], sAd[128];
    int tid = threadIdx.x;
    int wid = tid >> 5, lane = tid & 31;
    int wm = wid >> 1, wn = wid & 1;
    int m0 = blockIdx.x * 128, n0 = blockIdx.y * 64;
    int hd = blockIdx.y;

    if (tid < 128) { sAs[tid] = 0.f; sAd[tid] = 0.f; }

    float c[2][4][4];
#pragma unroll
    for (int f = 0; f < 2; f++)
#pragma unroll
        for (int g = 0; g < 4; g++)
#pragma unroll
            for (int i = 0; i < 4; i++) c[f][g][i] = 0.f;

    int lr = lane >> 2;   // 0..7
    int lc = lane & 3;    // 0..3

    for (int kt = 0; kt < F; kt += 32) {
        if (USE_FEAT) {
            // fp16-native: 512 x 16B, 2 per thread
#pragma unroll
            for (int i = 0; i < 2; i++) {
                int id = tid + i * 256;
                int row = id >> 2, seg = id & 3;
                int m = m0 + row;
                uint4 v = make_uint4(0, 0, 0, 0);
                if (m < NN)
                    v = *(const uint4*)(g_featH + (long)m * 128 + (kt >> 1) + seg * 4);
                *(uint4*)&As[row][seg * 8] = v;
            }
        } else {
            // fp32 source with cvt: 1024 float4 over 256 threads = 4 each
#pragma unroll
            for (int i = 0; i < 4; i++) {
                int id = tid + i * 256;
                int row = id >> 3, c4 = (id & 7) * 4;
                int m = m0 + row;
                float4 v = make_float4(0.f, 0.f, 0.f, 0.f);
                if (m < NN)
                    v = *(const float4*)(Aext + (long)m * F + kt + c4);
                *(__half2*)&As[row][c4]     = __floats2half2_rn(v.x, v.y);
                *(__half2*)&As[row][c4 + 2] = __floats2half2_rn(v.z, v.w);
            }
        }
        // stage B (32 rows x 64 halves = 128 B/row): 256 x 16B, 1 per thread
        {
            int row = tid >> 3, seg = tid & 7;
            const uint32_t* src = g_bh + bOff + (long)(kt + row) * 128
                                + (n0 >> 1) + seg * 4;
            *(uint4*)&Bs[row][seg * 8] = *(const uint4*)src;
        }
        __syncthreads();

#pragma unroll
        for (int s = 0; s < 2; s++) {       // two k16 steps per 32-chunk
            int kb = s * 16;
            uint32_t a[2][4];
#pragma unroll
            for (int f = 0; f < 2; f++) {
                int rb = wm * 32 + f * 16;
                a[f][0] = *(const uint32_t*)&As[rb + lr][kb + 2 * lc];
                a[f][1] = *(const uint32_t*)&As[rb + lr + 8][kb + 2 * lc];
                a[f][2] = *(const uint32_t*)&As[rb + lr][kb + 2 * lc + 8];
                a[f][3] = *(const uint32_t*)&As[rb + lr + 8][kb + 2 * lc + 8];
            }
            uint32_t b[4][2];
#pragma unroll
            for (int g = 0; g < 4; g++) {
                int cb = wn * 32 + g * 8 + lr;
                uint16_t lo0 = __half_as_ushort(Bs[kb + 2 * lc][cb]);
                uint16_t hi0 = __half_as_ushort(Bs[kb + 2 * lc + 1][cb]);
                uint16_t lo1 = __half_as_ushort(Bs[kb + 2 * lc + 8][cb]);
                uint16_t hi1 = __half_as_ushort(Bs[kb + 2 * lc + 9][cb]);
                b[g][0] = (uint32_t)lo0 | ((uint32_t)hi0 << 16);
                b[g][1] = (uint32_t)lo1 | ((uint32_t)hi1 << 16);
            }
#pragma unroll
            for (int f = 0; f < 2; f++)
#pragma unroll
                for (int g = 0; g < 4; g++) {
                    asm volatile(
                        "mma.sync.aligned.m16n8k16.row.col.f32.f16.f16.f32 "
                        "{%0,%1,%2,%3}, {%4,%5,%6,%7}, {%8,%9}, {%0,%1,%2,%3};"
                        : "+f"(c[f][g][0]), "+f"(c[f][g][1]),
                          "+f"(c[f][g][2]), "+f"(c[f][g][3])
                        : "r"(a[f][0]), "r"(a[f][1]), "r"(a[f][2]), "r"(a[f][3]),
                          "r"(b[g][0]), "r"(b[g][1]));
                }
        }
        __syncthreads();
    }

    // epilogue: write h as half2, fused per-row attention dots (fp32)
#pragma unroll
    for (int f = 0; f < 2; f++) {
        int row0 = m0 + wm * 32 + f * 16 + lr;
        float ps0 = 0.f, ps1 = 0.f, pd0 = 0.f, pd1 = 0.f;
#pragma unroll
        for (int g = 0; g < 4; g++) {
            int colh = wn * 32 + g * 8 + lc * 2;        // column within head
            float as0 = att_s[hd * 64 + colh], as1 = att_s[hd * 64 + colh + 1];
            float ad0 = att_d[hd * 64 + colh], ad1 = att_d[hd * 64 + colh + 1];
            ps0 += c[f][g][0] * as0 + c[f][g][1] * as1;
            pd0 += c[f][g][0] * ad0 + c[f][g][1] * ad1;
            ps1 += c[f][g][2] * as0 + c[f][g][3] * as1;
            pd1 += c[f][g][2] * ad0 + c[f][g][3] * ad1;
            uint32_t hidx = (uint32_t)(wn * 16 + g * 4 + lc) + hd * 32;
            if (row0 < NN) {
                __half2 hv = __floats2half2_rn(c[f][g][0], c[f][g][1]);
                g_h16[(long)row0 * 128 + hidx] = *(uint32_t*)&hv;
            }
            if (row0 + 8 < NN) {
                __half2 hv = __floats2half2_rn(c[f][g][2], c[f][g][3]);
                g_h16[(long)(row0 + 8) * 128 + hidx] = *(uint32_t*)&hv;
            }
        }
#pragma unroll
        for (int off = 1; off <= 2; off <<= 1) {
            ps0 += __shfl_xor_sync(0xffffffffu, ps0, off);
            ps1 += __shfl_xor_sync(0xffffffffu, ps1, off);
            pd0 += __shfl_xor_sync(0xffffffffu, pd0, off);
            pd1 += __shfl_xor_sync(0xffffffffu, pd1, off);
        }
        if (lc == 0) {
            int r = wm * 32 + f * 16 + lr;
            atomicAdd(&sAs[r], ps0);
            atomicAdd(&sAd[r], pd0);
            atomicAdd(&sAs[r + 8], ps1);
            atomicAdd(&sAd[r + 8], pd1);
        }
    }
    __syncthreads();
    if (tid < 128) {
        int m = m0 + tid;
        if (m < NN) {
            g_as[m * HEADS + hd] = sAs[tid];
            g_ad[m * HEADS + hd] = sAd[tid];
        }
    }
}

// ------- pass 1 + weights: one warp per node, all 4 heads -------------------
__global__ void agg1w_kernel() {
    int n = (blockIdx.x * blockDim.x + threadIdx.x) >> 5;
    int lane = threadIdx.x & 31;
    if (n >= NN) return;
    int hd = lane & 3, sub = lane >> 2;
    int beg = g_ptr[n], end = g_ptr[n + 1];
    float ad = g_ad[n * HEADS + hd];

    float m = -1e30f, s = 0.f;
    for (int j = beg + sub; j < end; j += 8) {
        int src = g_srcb[j];
        float e = g_as[src * HEADS + hd] + ad;
        e = (e > 0.f) ? e : 0.2f * e;
        g_w[j * HEADS + hd] = e;          // stash raw logit (coalesced)
        float mn = fmaxf(m, e);
        s = s * __expf(m - mn) + __expf(e - mn);
        m = mn;
    }
#pragma unroll
    for (int off = 4; off <= 16; off <<= 1) {
        float m2 = __shfl_xor_sync(0xffffffffu, m, off);
        float s2 = __shfl_xor_sync(0xffffffffu, s, off);
        float mn = fmaxf(m, m2);
        s = s * __expf(m - mn) + s2 * __expf(m2 - mn);
        m = mn;
    }
    float inv = 1.f / (s + 1e-16f);

    for (int j = beg + sub; j < end; j += 8) {
        float e = g_w[j * HEADS + hd];    // coalesced reload
        g_w[j * HEADS + hd] = __expf(e - m) * inv;
    }
}

// ------- pass 2: weighted gather — warp per (node, head), 8-wide MLP --------
template <bool TO_FEAT>
__global__ void agg2_kernel(const float* bias, float* outext) {
    int gw = (blockIdx.x * blockDim.x + threadIdx.x) >> 5;
    int lane = threadIdx.x & 31;
    if (gw >= NN * HEADS) return;
    int n = gw >> 2, hd = gw & 3;
    int beg = g_ptr[n], end = g_ptr[n + 1];
    const int hoff32 = hd * 32;

    float acc0 = 0.f, acc1 = 0.f;
    int j = beg;
    for (; j + 8 <= end; j += 8) {
        int si[8]; float wi[8]; uint32_t ui[8];
#pragma unroll
        for (int k = 0; k < 8; k++) si[k] = g_srcb[j + k];
#pragma unroll
        for (int k = 0; k < 8; k++) wi[k] = g_w[(j + k) * HEADS + hd];
#pragma unroll
        for (int k = 0; k < 8; k++)
            ui[k] = g_h16[(long)si[k] * 128 + hoff32 + lane];
#pragma unroll
        for (int k = 0; k < 8; k++) {
            float2 f = __half22float2(*(__half2*)&ui[k]);
            acc0 += wi[k] * f.x;
            acc1 += wi[k] * f.y;
        }
    }
    for (; j < end; ++j) {
        int s0 = g_srcb[j];
        float w0 = g_w[j * HEADS + hd];
        uint32_t u0 = g_h16[(long)s0 * 128 + hoff32 + lane];
        float2 f0 = __half22float2(*(__half2*)&u0);
        acc0 += w0 * f0.x;
        acc1 += w0 * f0.y;
    }

    int col = hd * 64 + lane * 2;
    float v0 = acc0 + bias[col];
    float v1 = acc1 + bias[col + 1];
    v0 = (v0 > 0.f) ? v0 : (__expf(v0) - 1.f);  // ELU
    v1 = (v1 > 0.f) ? v1 : (__expf(v1) - 1.f);
    if (TO_FEAT) {
        __half2 hv = __floats2half2_rn(v0, v1);
        g_featH[(long)n * 128 + hoff32 + lane] = *(uint32_t*)&hv;
    } else {
        *(float2*)&outext[(long)n * F + col] = make_float2(v0, v1);
    }
}

// ---------------- orchestration ----------------
extern "C" void kernel_launch(void* const* d_in, const int* in_sizes, int n_in,
                              void* d_out, int out_size) {
    const float* x   = (const float*)d_in[0];
    const void*  ei  = d_in[1];
    const float* W1  = (const float*)d_in[2];
    const float* a1s = (const float*)d_in[3];
    const float* a1d = (const float*)d_in[4];
    const float* b1  = (const float*)d_in[5];
    const float* W2  = (const float*)d_in[6];
    const float* a2s = (const float*)d_in[7];
    const float* a2d = (const float*)d_in[8];
    const float* b2  = (const float*)d_in[9];
    const float* W3  = (const float*)d_in[10];
    const float* a3s = (const float*)d_in[11];
    const float* a3d = (const float*)d_in[12];
    const float* b3  = (const float*)d_in[13];
    float* out = (float*)d_out;
    int E = in_sizes[1] / 2;
    int nthreads = (E >> 2) + (E & 3) + NN;
    int prepThreads = 3 * 32768;

    dim3 ggrid((NN + 127) / 128, F / 64);
    int p1Blocks = (NN * 32 + 255) / 256;
    int p2Blocks = (NN * HEADS * 32 + 255) / 256;

    // Fork: CSR chain on per-thread stream, weights-prep + GEMM1 on legacy.
    cudaEvent_t evFork, evJoin;
    cudaEventCreateWithFlags(&evFork, cudaEventDisableTiming);
    cudaEventCreateWithFlags(&evJoin, cudaEventDisableTiming);

    cudaEventRecord(evFork, 0);
    cudaStreamWaitEvent(cudaStreamPerThread, evFork, 0);

    detect_kernel<<<1, 32, 0, cudaStreamPerThread>>>(ei);
    count_kernel<<<(nthreads + 255) / 256, 256, 0, cudaStreamPerThread>>>(ei, E);
    scan_kernel<<<1, 512, 0, cudaStreamPerThread>>>();
    scatter_kernel<<<(nthreads + 255) / 256, 256, 0, cudaStreamPerThread>>>(ei, E);
    cudaEventRecord(evJoin, cudaStreamPerThread);

    prep_kernel<<<(prepThreads + 255) / 256, 256>>>(W1, W2, W3);
    gemm_f16_kernel<false><<<ggrid, 256>>>(x, 0, a1s, a1d);

    cudaStreamWaitEvent(0, evJoin, 0);   // agg needs CSR + GEMM1

    // layer 1
    agg1w_kernel<<<p1Blocks, 256>>>();
    agg2_kernel<true><<<p2Blocks, 256>>>(b1, nullptr);

    // layer 2
    gemm_f16_kernel<true><<<ggrid, 256>>>(nullptr, 32768, a2s, a2d);
    agg1w_kernel<<<p1Blocks, 256>>>();
    agg2_kernel<true><<<p2Blocks, 256>>>(b2, nullptr);

    // layer 3
    gemm_f16_kernel<true><<<ggrid, 256>>>(nullptr, 65536, a3s, a3d);
    agg1w_kernel<<<p1Blocks, 256>>>();
    agg2_kernel<false><<<p2Blocks, 256>>>(b3, out);
}